// round 16
// baseline (speedup 1.0000x reference)
#include <cuda_runtime.h>
#include <cuda_bf16.h>
#include <math.h>
#include <stdint.h>

#define D 128
#define MAXS 65536
#define MAXN 8192

// ---------------- scratch (device globals — no runtime allocation)
__device__ float g_ztxt[MAXN * D];
__device__ __nv_bfloat16 g_Tb[MAXN * D];
__device__ __nv_bfloat16 g_TbM[MAXN * D];
__device__ __nv_bfloat16 g_Ab[MAXN * D];
__device__ float g_inv[MAXS];
__device__ unsigned long long g_seg[MAXN];
__device__ double g_sum;

__device__ __forceinline__ uint32_t smem_u32(const void* p) {
    uint32_t a;
    asm("{ .reg .u64 t; cvta.to.shared.u64 t, %1; cvt.u32.u64 %0, t; }" : "=r"(a) : "l"(p));
    return a;
}

// ---------------- Phase 1: normalize text (warp/row) + fused scratch init
__global__ void k_norm_txt(const float* __restrict__ txt, int n) {
    int gtid = blockIdx.x * blockDim.x + threadIdx.x;
    if (gtid < n) g_seg[gtid] = ~0ull;
    if (gtid == 0) g_sum = 0.0;
    int w = gtid >> 5;
    int lane = threadIdx.x & 31;
    if (w >= n) return;
    float4 v = reinterpret_cast<const float4*>(txt + (size_t)w * D)[lane];
    float ss = v.x*v.x + v.y*v.y + v.z*v.z + v.w*v.w;
    #pragma unroll
    for (int o = 16; o > 0; o >>= 1) ss += __shfl_xor_sync(0xffffffffu, ss, o);
    float inv = 1.0f / (sqrtf(ss) + 1e-12f);
    float4 r = make_float4(v.x*inv, v.y*inv, v.z*inv, v.w*inv);
    reinterpret_cast<float4*>(g_ztxt + (size_t)w * D)[lane] = r;
    __nv_bfloat162 b0 = __floats2bfloat162_rn(r.x, r.y);
    __nv_bfloat162 b1 = __floats2bfloat162_rn(r.z, r.w);
    __nv_bfloat162* dst = reinterpret_cast<__nv_bfloat162*>(g_Tb + (size_t)w * D + lane * 4);
    dst[0] = b0; dst[1] = b1;
}

// ---------------- Phase 2: tp logit + segmented argmin (half-warp per image)
__global__ void k_img(const float* __restrict__ img, const int* __restrict__ key,
                      const float* __restrict__ sp, const float* __restrict__ bp, int s) {
    int hw = (blockIdx.x * blockDim.x + threadIdx.x) >> 4;
    int hl = threadIdx.x & 15;
    if (hw >= s) return;
    const float4* vi = reinterpret_cast<const float4*>(img + (size_t)hw * D);
    float4 v0 = vi[hl], v1 = vi[hl + 16];
    int k = key[hw];
    const float4* ti = reinterpret_cast<const float4*>(g_ztxt + (size_t)k * D);
    float4 t0 = ti[hl], t1 = ti[hl + 16];
    float ss = v0.x*v0.x + v0.y*v0.y + v0.z*v0.z + v0.w*v0.w
             + v1.x*v1.x + v1.y*v1.y + v1.z*v1.z + v1.w*v1.w;
    float dt = v0.x*t0.x + v0.y*t0.y + v0.z*t0.z + v0.w*t0.w
             + v1.x*t1.x + v1.y*t1.y + v1.z*t1.z + v1.w*t1.w;
    #pragma unroll
    for (int o = 8; o > 0; o >>= 1) {
        ss += __shfl_xor_sync(0xffffffffu, ss, o);
        dt += __shfl_xor_sync(0xffffffffu, dt, o);
    }
    if (hl == 0) {
        float inv = 1.0f / (sqrtf(ss) + 1e-12f);
        g_inv[hw] = inv;
        float tp = fmaf(dt * inv, *sp, *bp);
        float t = -tp;
        float pot = fmaxf(t, 0.0f) + log1pf(expf(-fabsf(t)));
        unsigned long long pk =
            ((unsigned long long)__float_as_uint(pot) << 32) | (unsigned)hw;
        atomicMin(&g_seg[k], pk);
    }
}

// ---------------- Phase 3: gather best image -> bf16 A rows; write col-masked B
__global__ void k_gather(const float* __restrict__ img, int n) {
    int w = (blockIdx.x * blockDim.x + threadIdx.x) >> 5;
    int lane = threadIdx.x & 31;
    if (w >= n) return;
    unsigned long long sv = g_seg[w];
    bool valid = (sv != ~0ull);
    float4 o = make_float4(0.f, 0.f, 0.f, 0.f);
    if (valid) {
        unsigned best = (unsigned)(sv & 0xffffffffu);
        float inv = g_inv[best];
        float4 v = reinterpret_cast<const float4*>(img + (size_t)best * D)[lane];
        o = make_float4(v.x*inv, v.y*inv, v.z*inv, v.w*inv);
    }
    __nv_bfloat162 b0 = __floats2bfloat162_rn(o.x, o.y);
    __nv_bfloat162 b1 = __floats2bfloat162_rn(o.z, o.w);
    __nv_bfloat162* dst = reinterpret_cast<__nv_bfloat162*>(g_Ab + (size_t)w * D + lane * 4);
    dst[0] = b0; dst[1] = b1;
    uint2 tv = make_uint2(0u, 0u);
    if (valid)
        tv = reinterpret_cast<const uint2*>(g_Tb + (size_t)w * D)[lane];
    reinterpret_cast<uint2*>(g_TbM + (size_t)w * D)[lane] = tv;
}

// ---------------- Phase 4: warp-specialized bf16 GEMM + fused loss
// 512 threads: warps 0-7 = MMA producers (tensor pipe only),
//              warps 8-15 = epilogue consumers (MUFU pipe only).
// A-resident supertile (1x4 B tiles), double-buffered B (cp.async) and
// double-buffered fp32 acc half-tiles (128x64, padded stride) in smem.
__device__ __forceinline__ void ldsm4(uint32_t* r, uint32_t addr) {
    asm volatile("ldmatrix.sync.aligned.m8n8.x4.shared.b16 {%0,%1,%2,%3}, [%4];"
                 : "=r"(r[0]), "=r"(r[1]), "=r"(r[2]), "=r"(r[3]) : "r"(addr));
}
__device__ __forceinline__ void mma16816(float* c, const uint32_t* a, const uint32_t* b) {
    asm volatile("mma.sync.aligned.m16n8k16.row.col.f32.bf16.bf16.f32 "
                 "{%0,%1,%2,%3}, {%4,%5,%6,%7}, {%8,%9}, {%0,%1,%2,%3};"
                 : "+f"(c[0]), "+f"(c[1]), "+f"(c[2]), "+f"(c[3])
                 : "r"(a[0]), "r"(a[1]), "r"(a[2]), "r"(a[3]), "r"(b[0]), "r"(b[1]));
}
__device__ __forceinline__ uint32_t sw_off(int row, int cb) {
    return (uint32_t)(row * 256 + (((cb ^ (row & 7)) & 15) << 4));
}
__device__ __forceinline__ void cp16(uint32_t dst, const void* src) {
    asm volatile("cp.async.cg.shared.global [%0], [%1], 16;" :: "r"(dst), "l"(src));
}
#define BAR_SYNC(id, cnt)   asm volatile("bar.sync %0, %1;"   :: "r"(id), "r"(cnt) : "memory")
#define BAR_ARRIVE(id, cnt) asm volatile("bar.arrive %0, %1;" :: "r"(id), "r"(cnt) : "memory")
#define NT 4
#define ACC_STRIDE 272   // bytes per acc row (68 floats: stride-4-bank skew)

__global__ void __launch_bounds__(512, 1)
k_gemm_loss(const float* __restrict__ sp, const float* __restrict__ bp) {
    extern __shared__ __align__(1024) char smem[];
    const uint32_t A_OFF = 0u;
    const uint32_t B_OFF0 = 32768u, B_OFF1 = 65536u;
    const uint32_t ACC0 = 98304u, ACC1 = 133120u;
    float* swred = (float*)(smem + 167936);
    uint32_t sb = smem_u32(smem);

    int tid = threadIdx.x, wid = tid >> 5, lane = tid & 31;
    int bm = blockIdx.y;
    int bng = blockIdx.x * NT;
    float ls0 = 0.f, ls1 = 0.f;

    if (wid < 8) {
        // ================= producers: MMA only =================
        int ptid = tid;                       // 0..255
        int wm  = (wid & 3) << 5;             // M offset 0/32/64/96
        int wn2 = (wid >> 2) << 5;            // N offset 0/32 within 64-col half
        int lrow = lane & 15;
        int lcb  = lane >> 4;
        int r7 = lrow & 7;
        int qr = lane >> 2, qc = (lane & 3) << 1;

        uint32_t swk[8];
        #pragma unroll
        for (int ks = 0; ks < 8; ks++)
            swk[ks] = (uint32_t)((((ks * 2 + lcb) ^ r7) & 15) << 4);
        uint32_t aR0 = sb + A_OFF + (uint32_t)(wm + lrow) * 256u;
        uint32_t aR1 = aR0 + 4096u;
        uint32_t bOff = (uint32_t)(wn2 + lrow) * 256u;

        // prologue: group0 = {A, B0}; group1 = {B1}
        {
            const uint4* Ag = reinterpret_cast<const uint4*>(g_Ab + (size_t)bm * 128 * D);
            const uint4* Bg = reinterpret_cast<const uint4*>(g_TbM + (size_t)bng * 128 * D);
            #pragma unroll
            for (int i = 0; i < 8; i++) {
                int ch = ptid + i * 256;
                uint32_t off = sw_off(ch >> 4, ch & 15);
                cp16(sb + A_OFF + off, Ag + ch);
                cp16(sb + B_OFF0 + off, Bg + ch);
            }
            asm volatile("cp.async.commit_group;");
            const uint4* Bg1 = reinterpret_cast<const uint4*>(g_TbM + (size_t)(bng + 1) * 128 * D);
            #pragma unroll
            for (int i = 0; i < 8; i++) {
                int ch = ptid + i * 256;
                uint32_t off = sw_off(ch >> 4, ch & 15);
                cp16(sb + B_OFF1 + off, Bg1 + ch);
            }
            asm volatile("cp.async.commit_group;");
        }

        #pragma unroll
        for (int t = 0; t < NT; t++) {
            if (t < NT - 2)      asm volatile("cp.async.wait_group 1;" ::: "memory");
            else                 asm volatile("cp.async.wait_group 0;" ::: "memory");
            BAR_SYNC(5, 256);                            // B tile visible to all producers

            uint32_t bbase = sb + ((t & 1) ? B_OFF1 : B_OFF0);
            #pragma unroll
            for (int h = 0; h < 2; h++) {
                const int u = t * 2 + h;
                uint32_t bH0 = bbase + (uint32_t)(h * 64) * 256u + bOff;
                uint32_t bH1 = bH0 + 16u * 256u;

                float acc[32];
                #pragma unroll
                for (int i = 0; i < 32; i++) acc[i] = 0.f;

                #pragma unroll
                for (int ks = 0; ks < 8; ks++) {
                    uint32_t sw = swk[ks];
                    uint32_t af0[4], af1[4], b0[4], b1[4];
                    ldsm4(af0, aR0 + sw);
                    ldsm4(af1, aR1 + sw);
                    ldsm4(b0, bH0 + sw);
                    ldsm4(b1, bH1 + sw);
                    uint32_t f0[2] = { b0[0], b0[2] }, f1[2] = { b0[1], b0[3] };
                    uint32_t f2[2] = { b1[0], b1[2] }, f3[2] = { b1[1], b1[3] };
                    mma16816(&acc[0],  af0, f0); mma16816(&acc[4],  af0, f1);
                    mma16816(&acc[8],  af0, f2); mma16816(&acc[12], af0, f3);
                    mma16816(&acc[16], af1, f0); mma16816(&acc[20], af1, f1);
                    mma16816(&acc[24], af1, f2); mma16816(&acc[28], af1, f3);
                }

                if (u >= 2) BAR_SYNC(3 + (u & 1), 512);  // wait buffer free
                uint32_t accb = sb + ((u & 1) ? ACC1 : ACC0);
                #pragma unroll
                for (int am = 0; am < 2; am++)
                    #pragma unroll
                    for (int na = 0; na < 4; na++)
                        #pragma unroll
                        for (int ci = 0; ci < 1 + 1; ci++) {
                            int row = wm + am * 16 + qr + ci * 8;
                            uint32_t ad = accb + (uint32_t)row * ACC_STRIDE
                                          + (uint32_t)(wn2 + na * 8 + qc) * 4u;
                            int ix = am * 16 + na * 4 + ci * 2;
                            asm volatile("st.shared.v2.f32 [%0], {%1,%2};"
                                         :: "r"(ad), "f"(acc[ix]), "f"(acc[ix + 1]) : "memory");
                        }
                asm volatile("membar.cta;" ::: "memory");
                BAR_ARRIVE(1 + (u & 1), 512);            // publish full
            }
            BAR_SYNC(5, 256);                            // all producers done with B[t]
            if (t + 2 < NT) {
                const uint4* Bg = reinterpret_cast<const uint4*>(
                    g_TbM + (size_t)(bng + t + 2) * 128 * D);
                uint32_t dstb = sb + ((t & 1) ? B_OFF1 : B_OFF0);
                #pragma unroll
                for (int i = 0; i < 8; i++) {
                    int ch = ptid + i * 256;
                    uint32_t off = sw_off(ch >> 4, ch & 15);
                    cp16(dstb + off, Bg + ch);
                }
                asm volatile("cp.async.commit_group;");
            }
        }
    } else {
        // ================= consumers: epilogue only =================
        const float scale = *sp, bias = *bp;
        const float sl = scale * 1.44269504f, bl = bias * 1.44269504f;
        int ewid = wid - 8;                   // 0..7 -> 16 rows each
        int rb = ewid * 16;
        int rq = lane >> 2;                   // 0..7
        int c16 = (lane & 3) * 16;

        #pragma unroll
        for (int t = 0; t < NT; t++) {
            bool dcta = (bm == bng + t);
            #pragma unroll
            for (int h = 0; h < 2; h++) {
                const int u = t * 2 + h;
                BAR_SYNC(1 + (u & 1), 512);              // wait full
                uint32_t accb = sb + ((u & 1) ? ACC1 : ACC0);
                #pragma unroll
                for (int ri = 0; ri < 2; ri++) {
                    int r = rb + ri * 8 + rq;
                    uint32_t rowad = accb + (uint32_t)r * ACC_STRIDE + (uint32_t)c16 * 4u;
                    #pragma unroll
                    for (int q = 0; q < 4; q++) {
                        float4 v;
                        asm volatile("ld.shared.v4.f32 {%0,%1,%2,%3}, [%4];"
                                     : "=f"(v.x), "=f"(v.y), "=f"(v.z), "=f"(v.w)
                                     : "r"(rowad + q * 16));
                        float r0, r1, r2, r3;
                        float xa = fmaf(v.x, sl, bl), xb = fmaf(v.y, sl, bl);
                        float xc = fmaf(v.z, sl, bl), xd = fmaf(v.w, sl, bl);
                        asm volatile("ex2.approx.f32 %0, %1;" : "=f"(r0) : "f"(xa));
                        asm volatile("ex2.approx.f32 %0, %1;" : "=f"(r1) : "f"(xb));
                        asm volatile("ex2.approx.f32 %0, %1;" : "=f"(r2) : "f"(xc));
                        asm volatile("ex2.approx.f32 %0, %1;" : "=f"(r3) : "f"(xd));
                        ls0 += r0 + r2;
                        ls1 += r1 + r3;
                        if (dcta) {
                            int c0 = c16 + q * 4;
                            int dcol = r - h * 64;       // diag hits col == r - h*64
                            if (dcol == c0)     ls0 -= fmaf(v.x, scale, bias);
                            if (dcol == c0 + 1) ls0 -= fmaf(v.y, scale, bias);
                            if (dcol == c0 + 2) ls0 -= fmaf(v.z, scale, bias);
                            if (dcol == c0 + 3) ls0 -= fmaf(v.w, scale, bias);
                        }
                    }
                }
                BAR_ARRIVE(3 + (u & 1), 512);            // mark free
            }
        }
    }

    __syncthreads();
    float lsum = ls0 + ls1;
    #pragma unroll
    for (int o = 16; o > 0; o >>= 1) lsum += __shfl_xor_sync(0xffffffffu, lsum, o);
    if (lane == 0) swred[wid] = lsum;
    __syncthreads();
    if (wid == 0) {
        float v = (lane < 16) ? swred[lane] : 0.f;
        #pragma unroll
        for (int o = 8; o > 0; o >>= 1) v += __shfl_xor_sync(0xffffffffu, v, o);
        if (lane == 0) atomicAdd(&g_sum, (double)v);
    }
}

// ---------------- Phase 5: finalize (parallel valid count + analytic correction)
__global__ void k_final(float* out, const float* __restrict__ bp, int n) {
    __shared__ int sred[256];
    int tid = threadIdx.x;
    int cnt = 0;
    for (int i = tid; i < n; i += 256)
        if (g_seg[i] != ~0ull) cnt++;
    cnt += __shfl_xor_sync(0xffffffffu, cnt, 16);
    cnt += __shfl_xor_sync(0xffffffffu, cnt, 8);
    cnt += __shfl_xor_sync(0xffffffffu, cnt, 4);
    cnt += __shfl_xor_sync(0xffffffffu, cnt, 2);
    cnt += __shfl_xor_sync(0xffffffffu, cnt, 1);
    if ((tid & 31) == 0) sred[tid >> 5] = cnt;
    __syncthreads();
    if (tid == 0) {
        int nv = 0;
        #pragma unroll
        for (int i = 0; i < 8; i++) nv += sred[i];
        float bias = *bp;
        int n_inv = n - nv;
        float bl = bias * 1.44269504f;
        float r0; asm("ex2.approx.f32 %0, %1;" : "=f"(r0) : "f"(bl));
        double c0 = (double)r0;
        double npairs_inv = (double)n * (double)n - (double)nv * (double)nv;
        double corr = npairs_inv * c0 - (double)n_inv * (double)bias;
        int dnv = nv < 1 ? 1 : nv;
        out[0] = (float)((g_sum - corr) / (double)dnv);
    }
}

extern "C" void kernel_launch(void* const* d_in, const int* in_sizes, int n_in,
                              void* d_out, int out_size) {
    const float* img = (const float*)d_in[0];
    const float* txt = (const float*)d_in[1];
    const int*   key = (const int*)d_in[2];
    const float* sc  = (const float*)d_in[3];
    const float* bi  = (const float*)d_in[4];
    int s = in_sizes[2];          // 65536
    int n = in_sizes[1] / D;      // 8192

    const int SMEM_BYTES = 168000;
    cudaFuncSetAttribute(k_gemm_loss, cudaFuncAttributeMaxDynamicSharedMemorySize, SMEM_BYTES);

    k_norm_txt<<<(n * 32 + 255) / 256, 256>>>(txt, n);
    k_img<<<(s * 16 + 255) / 256, 256>>>(img, key, sc, bi, s);
    k_gather<<<(n * 32 + 255) / 256, 256>>>(img, n);
    dim3 grid(n / 128 / NT, n / 128);
    k_gemm_loss<<<grid, 512, SMEM_BYTES>>>(sc, bi);
    k_final<<<1, 256>>>((float*)d_out, bi, n);
}

// round 17
// speedup vs baseline: 1.3209x; 1.3209x over previous
#include <cuda_runtime.h>
#include <cuda_bf16.h>
#include <math.h>
#include <stdint.h>

#define D 128
#define MAXS 65536
#define MAXN 8192

// ---------------- scratch (device globals — no runtime allocation)
__device__ float g_ztxt[MAXN * D];
__device__ __nv_bfloat16 g_Tb[MAXN * D];
__device__ __nv_bfloat16 g_TbM[MAXN * D];
__device__ __nv_bfloat16 g_Ab[MAXN * D];
__device__ float g_inv[MAXS];
__device__ unsigned long long g_seg[MAXN];
__device__ double g_sum;

__device__ __forceinline__ uint32_t smem_u32(const void* p) {
    uint32_t a;
    asm("{ .reg .u64 t; cvta.to.shared.u64 t, %1; cvt.u32.u64 %0, t; }" : "=r"(a) : "l"(p));
    return a;
}

// ---------------- Phase 1: normalize text (warp/row) + fused scratch init
__global__ void k_norm_txt(const float* __restrict__ txt, int n) {
    int gtid = blockIdx.x * blockDim.x + threadIdx.x;
    if (gtid < n) g_seg[gtid] = ~0ull;
    if (gtid == 0) g_sum = 0.0;
    int w = gtid >> 5;
    int lane = threadIdx.x & 31;
    if (w >= n) return;
    float4 v = reinterpret_cast<const float4*>(txt + (size_t)w * D)[lane];
    float ss = v.x*v.x + v.y*v.y + v.z*v.z + v.w*v.w;
    #pragma unroll
    for (int o = 16; o > 0; o >>= 1) ss += __shfl_xor_sync(0xffffffffu, ss, o);
    float inv = 1.0f / (sqrtf(ss) + 1e-12f);
    float4 r = make_float4(v.x*inv, v.y*inv, v.z*inv, v.w*inv);
    reinterpret_cast<float4*>(g_ztxt + (size_t)w * D)[lane] = r;
    __nv_bfloat162 b0 = __floats2bfloat162_rn(r.x, r.y);
    __nv_bfloat162 b1 = __floats2bfloat162_rn(r.z, r.w);
    __nv_bfloat162* dst = reinterpret_cast<__nv_bfloat162*>(g_Tb + (size_t)w * D + lane * 4);
    dst[0] = b0; dst[1] = b1;
}

// ---------------- Phase 2: tp logit + segmented argmin (half-warp per image)
__global__ void k_img(const float* __restrict__ img, const int* __restrict__ key,
                      const float* __restrict__ sp, const float* __restrict__ bp, int s) {
    int hw = (blockIdx.x * blockDim.x + threadIdx.x) >> 4;
    int hl = threadIdx.x & 15;
    if (hw >= s) return;
    const float4* vi = reinterpret_cast<const float4*>(img + (size_t)hw * D);
    float4 v0 = vi[hl], v1 = vi[hl + 16];
    int k = key[hw];
    const float4* ti = reinterpret_cast<const float4*>(g_ztxt + (size_t)k * D);
    float4 t0 = ti[hl], t1 = ti[hl + 16];
    float ss = v0.x*v0.x + v0.y*v0.y + v0.z*v0.z + v0.w*v0.w
             + v1.x*v1.x + v1.y*v1.y + v1.z*v1.z + v1.w*v1.w;
    float dt = v0.x*t0.x + v0.y*t0.y + v0.z*t0.z + v0.w*t0.w
             + v1.x*t1.x + v1.y*t1.y + v1.z*t1.z + v1.w*t1.w;
    #pragma unroll
    for (int o = 8; o > 0; o >>= 1) {
        ss += __shfl_xor_sync(0xffffffffu, ss, o);
        dt += __shfl_xor_sync(0xffffffffu, dt, o);
    }
    if (hl == 0) {
        float inv = 1.0f / (sqrtf(ss) + 1e-12f);
        g_inv[hw] = inv;
        float tp = fmaf(dt * inv, *sp, *bp);
        float t = -tp;
        float pot = fmaxf(t, 0.0f) + log1pf(expf(-fabsf(t)));
        unsigned long long pk =
            ((unsigned long long)__float_as_uint(pot) << 32) | (unsigned)hw;
        atomicMin(&g_seg[k], pk);
    }
}

// ---------------- Phase 3: gather best image -> bf16 A rows; write col-masked B
__global__ void k_gather(const float* __restrict__ img, int n) {
    int w = (blockIdx.x * blockDim.x + threadIdx.x) >> 5;
    int lane = threadIdx.x & 31;
    if (w >= n) return;
    unsigned long long sv = g_seg[w];
    bool valid = (sv != ~0ull);
    float4 o = make_float4(0.f, 0.f, 0.f, 0.f);
    if (valid) {
        unsigned best = (unsigned)(sv & 0xffffffffu);
        float inv = g_inv[best];
        float4 v = reinterpret_cast<const float4*>(img + (size_t)best * D)[lane];
        o = make_float4(v.x*inv, v.y*inv, v.z*inv, v.w*inv);
    }
    __nv_bfloat162 b0 = __floats2bfloat162_rn(o.x, o.y);
    __nv_bfloat162 b1 = __floats2bfloat162_rn(o.z, o.w);
    __nv_bfloat162* dst = reinterpret_cast<__nv_bfloat162*>(g_Ab + (size_t)w * D + lane * 4);
    dst[0] = b0; dst[1] = b1;
    uint2 tv = make_uint2(0u, 0u);
    if (valid)
        tv = reinterpret_cast<const uint2*>(g_Tb + (size_t)w * D)[lane];
    reinterpret_cast<uint2*>(g_TbM + (size_t)w * D)[lane] = tv;
}

// ---------------- Phase 4: bf16 mma.sync GEMM, A-resident supertile (1x4 B tiles).
// Warp 0 is the sole B prefetcher; free/ready are split arrive/sync named barriers
// so non-producer warps are NEVER re-converged after the prologue. Warps 4-7 get a
// one-time ~1024-cyc skew that persists -> per-SMSP MMA/epilogue phase overlap.
__device__ __forceinline__ void ldsm4(uint32_t* r, uint32_t addr) {
    asm volatile("ldmatrix.sync.aligned.m8n8.x4.shared.b16 {%0,%1,%2,%3}, [%4];"
                 : "=r"(r[0]), "=r"(r[1]), "=r"(r[2]), "=r"(r[3]) : "r"(addr));
}
__device__ __forceinline__ void mma16816(float* c, const uint32_t* a, const uint32_t* b) {
    asm volatile("mma.sync.aligned.m16n8k16.row.col.f32.bf16.bf16.f32 "
                 "{%0,%1,%2,%3}, {%4,%5,%6,%7}, {%8,%9}, {%0,%1,%2,%3};"
                 : "+f"(c[0]), "+f"(c[1]), "+f"(c[2]), "+f"(c[3])
                 : "r"(a[0]), "r"(a[1]), "r"(a[2]), "r"(a[3]), "r"(b[0]), "r"(b[1]));
}
__device__ __forceinline__ uint32_t sw_off(int row, int cb) {
    return (uint32_t)(row * 256 + (((cb ^ (row & 7)) & 15) << 4));
}
__device__ __forceinline__ void cp16(uint32_t dst, const void* src) {
    asm volatile("cp.async.cg.shared.global [%0], [%1], 16;" :: "r"(dst), "l"(src));
}
#define BAR_SYNC(id)   asm volatile("bar.sync %0, 256;"   :: "r"(id) : "memory")
#define BAR_ARRIVE(id) asm volatile("bar.arrive %0, 256;" :: "r"(id) : "memory")
#define NT 4

__global__ void __launch_bounds__(256, 2)
k_gemm_loss(const float* __restrict__ sp, const float* __restrict__ bp) {
    extern __shared__ __align__(1024) char smem[];
    const uint32_t A_OFF = 0u;
    const uint32_t B_OFF0 = 32768u, B_OFF1 = 65536u;
    float* swred = (float*)(smem + 98304);
    uint32_t sb = smem_u32(smem);

    int tid = threadIdx.x, wid = tid >> 5, lane = tid & 31;
    int bm = blockIdx.y;
    int bng = blockIdx.x * NT;
    int wm = (wid & 3) << 5;
    int wn = (wid >> 2) << 6;
    int lrow = lane & 15;
    int lcb  = lane >> 4;
    int r7 = lrow & 7;

    uint32_t swk[8];
    #pragma unroll
    for (int ks = 0; ks < 8; ks++)
        swk[ks] = (uint32_t)((((ks * 2 + lcb) ^ r7) & 15) << 4);
    uint32_t aR0 = sb + A_OFF + (uint32_t)(wm + lrow) * 256u;
    uint32_t aR1 = aR0 + 4096u;
    uint32_t rowOff[4];
    #pragma unroll
    for (int nb = 0; nb < 4; nb++)
        rowOff[nb] = (uint32_t)(wn + nb * 16 + lrow) * 256u;

    // prologue: single group {A, B0, B1}; ONE full convergence point
    {
        const uint4* Ag  = reinterpret_cast<const uint4*>(g_Ab  + (size_t)bm * 128 * D);
        const uint4* Bg0 = reinterpret_cast<const uint4*>(g_TbM + (size_t)bng * 128 * D);
        const uint4* Bg1 = reinterpret_cast<const uint4*>(g_TbM + (size_t)(bng + 1) * 128 * D);
        #pragma unroll
        for (int i = 0; i < 8; i++) {
            int ch = tid + i * 256;
            uint32_t off = sw_off(ch >> 4, ch & 15);
            cp16(sb + A_OFF + off, Ag + ch);
            cp16(sb + B_OFF0 + off, Bg0 + ch);
            cp16(sb + B_OFF1 + off, Bg1 + ch);
        }
        asm volatile("cp.async.commit_group;");
    }
    asm volatile("cp.async.wait_group 0;" ::: "memory");
    __syncthreads();

    // persistent phase skew: one warp-group per SMSP delayed ~1024 cyc.
    if (wid >= 4) {
        float z = 1.0f;
        #pragma unroll 1
        for (int i = 0; i < 64; i++)
            asm volatile("ex2.approx.f32 %0, %1;" : "+f"(z) : "f"(z * 1e-30f));
        if (z == 12345.0f) swred[32 + wid] = z;   // opaque, never true
    }

    const float scale = *sp, bias = *bp;
    const float sl = scale * 1.44269504f, bl = bias * 1.44269504f;
    int qr = lane >> 2;
    int qc = (lane & 3) << 1;
    float lsum = 0.f;

    #pragma unroll
    for (int t = 0; t < NT; t++) {
        // readiness: tiles 0,1 covered by prologue; 2,3 signaled by warp 0
        if (t >= 2) {
            if (wid == 0) {
                if (t == 2) asm volatile("cp.async.wait_group 1;" ::: "memory");
                else        asm volatile("cp.async.wait_group 0;" ::: "memory");
                BAR_ARRIVE(2 + t);            // ready_t (ids 4,5)
            } else {
                BAR_SYNC(2 + t);
            }
        }

        uint32_t bbase = sb + ((t & 1) ? B_OFF1 : B_OFF0);
        uint32_t bR[4];
        #pragma unroll
        for (int nb = 0; nb < 4; nb++) bR[nb] = bbase + rowOff[nb];

        float acc[2][8][4];
        #pragma unroll
        for (int i = 0; i < 2; i++)
            #pragma unroll
            for (int j = 0; j < 8; j++)
                #pragma unroll
                for (int k = 0; k < 4; k++) acc[i][j][k] = 0.f;

        #pragma unroll
        for (int ks = 0; ks < 8; ks++) {
            uint32_t sw = swk[ks];
            uint32_t af[2][4];
            ldsm4(af[0], aR0 + sw);
            ldsm4(af[1], aR1 + sw);
            #pragma unroll
            for (int nb = 0; nb < 4; nb++) {
                uint32_t bf[4];
                ldsm4(bf, bR[nb] + sw);
                uint32_t b0[2] = { bf[0], bf[2] };
                uint32_t b1[2] = { bf[1], bf[3] };
                mma16816(acc[0][nb * 2 + 0], af[0], b0);
                mma16816(acc[0][nb * 2 + 1], af[0], b1);
                mma16816(acc[1][nb * 2 + 0], af[1], b0);
                mma16816(acc[1][nb * 2 + 1], af[1], b1);
            }
        }

        // free_t (ids 1,2): producers sync, everyone else just arrives and moves on
        if (t < 2) {
            if (wid == 0) {
                BAR_SYNC(1 + t);              // wait all warps done reading B[t]
                const uint4* Bg = reinterpret_cast<const uint4*>(
                    g_TbM + (size_t)(bng + t + 2) * 128 * D);
                uint32_t dstb = sb + ((t & 1) ? B_OFF1 : B_OFF0);
                #pragma unroll
                for (int i = 0; i < 64; i++) {
                    int ch = lane + i * 32;
                    uint32_t off = sw_off(ch >> 4, ch & 15);
                    cp16(dstb + off, Bg + ch);
                }
                asm volatile("cp.async.commit_group;");
            } else {
                BAR_ARRIVE(1 + t);
            }
        }

        // lean fused epilogue: softplus(x) ~= r = 2^(sl*dv+bl); diag: softplus(-x)=r-x
        int bn = bng + t;
        if (bm != bn) {
            #pragma unroll
            for (int am = 0; am < 2; am++)
                #pragma unroll
                for (int na = 0; na < 8; na++)
                    #pragma unroll
                    for (int k = 0; k < 4; k++) {
                        float x2 = fmaf(acc[am][na][k], sl, bl);
                        float r; asm("ex2.approx.f32 %0, %1;" : "=f"(r) : "f"(x2));
                        lsum += r;
                    }
        } else {
            #pragma unroll
            for (int am = 0; am < 2; am++) {
                #pragma unroll
                for (int na = 0; na < 8; na++) {
                    #pragma unroll
                    for (int k = 0; k < 4; k++) {
                        int ci = k >> 1, cj = k & 1;
                        int lr = wm + am * 16 + qr + ci * 8;
                        int lc = wn + na * 8 + qc + cj;
                        float dv = acc[am][na][k];
                        float x2 = fmaf(dv, sl, bl);
                        float r; asm("ex2.approx.f32 %0, %1;" : "=f"(r) : "f"(x2));
                        lsum += r;
                        if (lr == lc)              // softplus(-x) = softplus(x) - x
                            lsum -= fmaf(dv, scale, bias);
                    }
                }
            }
        }
    }

    #pragma unroll
    for (int o = 16; o > 0; o >>= 1) lsum += __shfl_xor_sync(0xffffffffu, lsum, o);
    if (lane == 0) swred[wid] = lsum;
    __syncthreads();
    if (wid == 0) {
        float v = (lane < 8) ? swred[lane] : 0.f;
        #pragma unroll
        for (int o = 4; o > 0; o >>= 1) v += __shfl_xor_sync(0xffffffffu, v, o);
        if (lane == 0) atomicAdd(&g_sum, (double)v);
    }
}

// ---------------- Phase 5: finalize (parallel valid count + analytic correction)
__global__ void k_final(float* out, const float* __restrict__ bp, int n) {
    __shared__ int sred[256];
    int tid = threadIdx.x;
    int cnt = 0;
    for (int i = tid; i < n; i += 256)
        if (g_seg[i] != ~0ull) cnt++;
    cnt += __shfl_xor_sync(0xffffffffu, cnt, 16);
    cnt += __shfl_xor_sync(0xffffffffu, cnt, 8);
    cnt += __shfl_xor_sync(0xffffffffu, cnt, 4);
    cnt += __shfl_xor_sync(0xffffffffu, cnt, 2);
    cnt += __shfl_xor_sync(0xffffffffu, cnt, 1);
    if ((tid & 31) == 0) sred[tid >> 5] = cnt;
    __syncthreads();
    if (tid == 0) {
        int nv = 0;
        #pragma unroll
        for (int i = 0; i < 8; i++) nv += sred[i];
        float bias = *bp;
        int n_inv = n - nv;
        float bl = bias * 1.44269504f;
        float r0; asm("ex2.approx.f32 %0, %1;" : "=f"(r0) : "f"(bl));
        double c0 = (double)r0;
        double npairs_inv = (double)n * (double)n - (double)nv * (double)nv;
        double corr = npairs_inv * c0 - (double)n_inv * (double)bias;
        int dnv = nv < 1 ? 1 : nv;
        out[0] = (float)((g_sum - corr) / (double)dnv);
    }
}

extern "C" void kernel_launch(void* const* d_in, const int* in_sizes, int n_in,
                              void* d_out, int out_size) {
    const float* img = (const float*)d_in[0];
    const float* txt = (const float*)d_in[1];
    const int*   key = (const int*)d_in[2];
    const float* sc  = (const float*)d_in[3];
    const float* bi  = (const float*)d_in[4];
    int s = in_sizes[2];          // 65536
    int n = in_sizes[1] / D;      // 8192

    const int SMEM_BYTES = 98304 + 256;
    cudaFuncSetAttribute(k_gemm_loss, cudaFuncAttributeMaxDynamicSharedMemorySize, SMEM_BYTES);

    k_norm_txt<<<(n * 32 + 255) / 256, 256>>>(txt, n);
    k_img<<<(s * 16 + 255) / 256, 256>>>(img, key, sc, bi, s);
    k_gather<<<(n * 32 + 255) / 256, 256>>>(img, n);
    dim3 grid(n / 128 / NT, n / 128);
    k_gemm_loss<<<grid, 256, SMEM_BYTES>>>(sc, bi);
    k_final<<<1, 256>>>((float*)d_out, bi, n);
}